// round 11
// baseline (speedup 1.0000x reference)
#include <cuda_runtime.h>
#include <math.h>

// Problem constants (B=2, N=4096, C=256, K=64; hidden = 256, out = 256)
#define PB 2
#define PN 4096
#define PC 256
#define PK 64
#define NS 8                 // split-K over points: 8 segments of 512 points
#define SEG (PN / NS)        // 512 points per segment

// Scratch: partial maxima [B*K][NS][64 float4], counts, and hidden activations
__device__ float4 g_part4[PB * PK * NS * 64];
__device__ int    g_cnt[PB * PK * NS];
__device__ float4 g_h[PB * PK * 64];          // hidden layer (relu'd), 128 rows x 64 f4

// ---------------- Kernel A: segment pooling ----------------
__global__ __launch_bounds__(256)
void pool_partial_kernel(const float* __restrict__ points,   // (B, N, 3)
                         const float* __restrict__ feats,    // (B, N, C)
                         const float* __restrict__ props)    // (B, K, 7)
{
    const int blk = blockIdx.x;      // bk * NS + s
    const int bk  = blk >> 3;
    const int s   = blk & (NS - 1);
    const int b   = bk / PK;
    const int t   = threadIdx.x;
    const int q   = t & 63;          // channel quad
    const int sl  = t >> 6;          // slice 0..3

    __shared__ int    s_idx[SEG];
    __shared__ int    s_count;
    __shared__ float  s_box[6];
    __shared__ float4 s_part[256];

    if (t == 0) s_count = 0;
    if (t < 3) {
        float c = props[bk * 7 + t];
        float h = props[bk * 7 + 3 + t] * 0.5f;
        s_box[t]     = c - h;
        s_box[t + 3] = c + h;
    }
    __syncthreads();

    const float lx = s_box[0], ly = s_box[1], lz = s_box[2];
    const float hx = s_box[3], hy = s_box[4], hz = s_box[5];

    const float* pb = points + (size_t)b * PN * 3;
    const int n0 = s * SEG;
    #pragma unroll
    for (int it = 0; it < SEG / 256; it++) {
        int n = n0 + it * 256 + t;
        float px = pb[n * 3 + 0];
        float py = pb[n * 3 + 1];
        float pz = pb[n * 3 + 2];
        bool inside = (px > lx) & (px < hx) &
                      (py > ly) & (py < hy) &
                      (pz > lz) & (pz < hz);
        if (inside) {
            int pos = atomicAdd(&s_count, 1);
            s_idx[pos] = n;
        }
    }
    __syncthreads();
    const int cnt = s_count;

    const float4* fb4 = (const float4*)(feats + (size_t)b * PN * PC);
    float4 acc = make_float4(-INFINITY, -INFINITY, -INFINITY, -INFINITY);
    {
        int i = sl;
        for (; i + 12 < cnt; i += 16) {
            int i0 = s_idx[i + 0];
            int i1 = s_idx[i + 4];
            int i2 = s_idx[i + 8];
            int i3 = s_idx[i + 12];
            float4 v0 = fb4[(size_t)i0 * 64 + q];
            float4 v1 = fb4[(size_t)i1 * 64 + q];
            float4 v2 = fb4[(size_t)i2 * 64 + q];
            float4 v3 = fb4[(size_t)i3 * 64 + q];
            acc.x = fmaxf(acc.x, fmaxf(fmaxf(v0.x, v1.x), fmaxf(v2.x, v3.x)));
            acc.y = fmaxf(acc.y, fmaxf(fmaxf(v0.y, v1.y), fmaxf(v2.y, v3.y)));
            acc.z = fmaxf(acc.z, fmaxf(fmaxf(v0.z, v1.z), fmaxf(v2.z, v3.z)));
            acc.w = fmaxf(acc.w, fmaxf(fmaxf(v0.w, v1.w), fmaxf(v2.w, v3.w)));
        }
        for (; i < cnt; i += 4) {
            float4 v = fb4[(size_t)s_idx[i] * 64 + q];
            acc.x = fmaxf(acc.x, v.x);
            acc.y = fmaxf(acc.y, v.y);
            acc.z = fmaxf(acc.z, v.z);
            acc.w = fmaxf(acc.w, v.w);
        }
    }
    s_part[t] = acc;
    __syncthreads();

    if (t < 64) {
        float4 a  = s_part[t];
        float4 c1 = s_part[64 + t];
        float4 c2 = s_part[128 + t];
        float4 c3 = s_part[192 + t];
        a.x = fmaxf(fmaxf(a.x, c1.x), fmaxf(c2.x, c3.x));
        a.y = fmaxf(fmaxf(a.y, c1.y), fmaxf(c2.y, c3.y));
        a.z = fmaxf(fmaxf(a.z, c1.z), fmaxf(c2.z, c3.z));
        a.w = fmaxf(fmaxf(a.w, c1.w), fmaxf(c2.w, c3.w));
        g_part4[(size_t)blk * 64 + t] = a;
    }
    if (t == 0) g_cnt[blk] = cnt;
}

// ---------------- Layer kernels: CTA = (row-pair, output-half) ----------------
// 1024 threads: q = t&31 (32 output quads of my half), sl = t>>5 (32 c-slices of 8)
// Per-thread: 8 LDG.128 of W + 16 warp-uniform LDS + 64 FMA. Weight slice 128KB/CTA.

__global__ __launch_bounds__(1024)
void mlp1_kernel(const float* __restrict__ W1, const float* __restrict__ b1)
{
    const int p  = blockIdx.x >> 1;      // row pair 0..63
    const int hf = blockIdx.x & 1;       // output half
    const int r0 = p * 2;
    const int t  = threadIdx.x;
    const int q  = t & 31;
    const int sl = t >> 5;

    __shared__ float4 s_a[1024];         // 16 KB (row 0 partials)
    __shared__ float4 s_b[1024];         // 16 KB (row 1 partials)
    __shared__ float4 s_x[2][64];        // two pooled input vectors
    __shared__ int    s_cnt[2];

    // fold NS=8 pooled partials for both rows (registers first, then publish)
    float4 xa;
    if (t < 128) {
        int row = t >> 6, qq = t & 63;
        const float4* src = &g_part4[(size_t)(r0 + row) * (NS * 64)];
        xa = src[qq];
        #pragma unroll
        for (int g = 1; g < NS; g++) {
            float4 c = src[g * 64 + qq];
            xa.x = fmaxf(xa.x, c.x);
            xa.y = fmaxf(xa.y, c.y);
            xa.z = fmaxf(xa.z, c.z);
            xa.w = fmaxf(xa.w, c.w);
        }
    }
    if (t >= 1022) {                      // two spare threads sum counts
        int row = t - 1022;
        int c = 0;
        #pragma unroll
        for (int i = 0; i < NS; i++) c += g_cnt[(r0 + row) * NS + i];
        s_cnt[row] = c;
    }
    __syncthreads();
    if (t < 128) {
        int row = t >> 6, qq = t & 63;
        if (s_cnt[row] == 0) xa = make_float4(0.f, 0.f, 0.f, 0.f);
        s_x[row][qq] = xa;
    }
    __syncthreads();

    // layer-1 partial: my 8 c's, 32 output quads of half hf, 2 rows
    const float4* W4 = (const float4*)W1;
    const float*  x0 = (const float*)s_x[0];
    const float*  x1 = (const float*)s_x[1];
    const int colq = hf * 32 + q;
    const int c0 = sl * 8;
    float4 a0 = make_float4(0.f, 0.f, 0.f, 0.f);
    float4 a1 = make_float4(0.f, 0.f, 0.f, 0.f);
    #pragma unroll
    for (int c = 0; c < 8; c++) {
        float4 w = W4[(size_t)(c0 + c) * 64 + colq];
        float f0 = x0[c0 + c];
        float f1 = x1[c0 + c];
        a0.x = fmaf(f0, w.x, a0.x); a0.y = fmaf(f0, w.y, a0.y);
        a0.z = fmaf(f0, w.z, a0.z); a0.w = fmaf(f0, w.w, a0.w);
        a1.x = fmaf(f1, w.x, a1.x); a1.y = fmaf(f1, w.y, a1.y);
        a1.z = fmaf(f1, w.z, a1.z); a1.w = fmaf(f1, w.w, a1.w);
    }
    s_a[t] = a0;
    s_b[t] = a1;
    __syncthreads();

    if (t < 64) {
        int rr = t >> 5, qq = t & 31;
        const float4* buf = rr ? s_b : s_a;
        float4 a = buf[qq];
        #pragma unroll
        for (int g = 1; g < 32; g++) {
            float4 c = buf[g * 32 + qq];
            a.x += c.x; a.y += c.y; a.z += c.z; a.w += c.w;
        }
        float4 bb = ((const float4*)b1)[hf * 32 + qq];
        a.x = fmaxf(a.x + bb.x, 0.f);
        a.y = fmaxf(a.y + bb.y, 0.f);
        a.z = fmaxf(a.z + bb.z, 0.f);
        a.w = fmaxf(a.w + bb.w, 0.f);
        g_h[(size_t)(r0 + rr) * 64 + hf * 32 + qq] = a;
    }
}

__global__ __launch_bounds__(1024)
void mlp2_kernel(const float* __restrict__ W2, const float* __restrict__ b2,
                 float* __restrict__ out)
{
    const int p  = blockIdx.x >> 1;
    const int hf = blockIdx.x & 1;
    const int r0 = p * 2;
    const int t  = threadIdx.x;
    const int q  = t & 31;
    const int sl = t >> 5;

    __shared__ float4 s_a[1024];
    __shared__ float4 s_b[1024];
    __shared__ float4 s_x[2][64];

    if (t < 128) {
        int row = t >> 6, qq = t & 63;
        s_x[row][qq] = g_h[(size_t)(r0 + row) * 64 + qq];
    }
    __syncthreads();

    const float4* W4 = (const float4*)W2;
    const float*  x0 = (const float*)s_x[0];
    const float*  x1 = (const float*)s_x[1];
    const int colq = hf * 32 + q;
    const int c0 = sl * 8;
    float4 a0 = make_float4(0.f, 0.f, 0.f, 0.f);
    float4 a1 = make_float4(0.f, 0.f, 0.f, 0.f);
    #pragma unroll
    for (int c = 0; c < 8; c++) {
        float4 w = W4[(size_t)(c0 + c) * 64 + colq];
        float f0 = x0[c0 + c];
        float f1 = x1[c0 + c];
        a0.x = fmaf(f0, w.x, a0.x); a0.y = fmaf(f0, w.y, a0.y);
        a0.z = fmaf(f0, w.z, a0.z); a0.w = fmaf(f0, w.w, a0.w);
        a1.x = fmaf(f1, w.x, a1.x); a1.y = fmaf(f1, w.y, a1.y);
        a1.z = fmaf(f1, w.z, a1.z); a1.w = fmaf(f1, w.w, a1.w);
    }
    s_a[t] = a0;
    s_b[t] = a1;
    __syncthreads();

    if (t < 64) {
        int rr = t >> 5, qq = t & 31;
        const float4* buf = rr ? s_b : s_a;
        float4 a = buf[qq];
        #pragma unroll
        for (int g = 1; g < 32; g++) {
            float4 c = buf[g * 32 + qq];
            a.x += c.x; a.y += c.y; a.z += c.z; a.w += c.w;
        }
        float4 bb = ((const float4*)b2)[hf * 32 + qq];
        a.x = fmaxf(a.x + bb.x, 0.f);
        a.y = fmaxf(a.y + bb.y, 0.f);
        a.z = fmaxf(a.z + bb.z, 0.f);
        a.w = fmaxf(a.w + bb.w, 0.f);
        ((float4*)out)[(size_t)(r0 + rr) * 64 + hf * 32 + qq] = a;
    }
}

extern "C" void kernel_launch(void* const* d_in, const int* in_sizes, int n_in,
                              void* d_out, int out_size)
{
    const float* points = (const float*)d_in[0];   // (B, N, 3)
    const float* feats  = (const float*)d_in[1];   // (B, N, C)
    const float* props  = (const float*)d_in[2];   // (B, K, 7)
    const float* W1     = (const float*)d_in[3];   // (C, 256)
    const float* b1     = (const float*)d_in[4];   // (256)
    const float* W2     = (const float*)d_in[5];   // (256, 256)
    const float* b2     = (const float*)d_in[6];   // (256)
    float*       out    = (float*)d_out;           // (B, K, 256)

    pool_partial_kernel<<<PB * PK * NS, 256>>>(points, feats, props);
    mlp1_kernel<<<PB * PK, 1024>>>(W1, b1);
    mlp2_kernel<<<PB * PK, 1024>>>(W2, b2, out);
}